// round 5
// baseline (speedup 1.0000x reference)
#include <cuda_runtime.h>
#include <cstdint>

typedef unsigned long long u64;

#define L_ 1024
#define B_ 2048
#define NE (L_ * B_)

// scratch: input-to-hidden gate projections [L*B][48]
__device__ float g_gates[(size_t)NE * 48];

__device__ __forceinline__ float ex2f(float x) {
    float y; asm("ex2.approx.f32 %0, %1;" : "=f"(y) : "f"(x)); return y;
}
__device__ __forceinline__ float rcpf(float x) {
    float y; asm("rcp.approx.f32 %0, %1;" : "=f"(y) : "f"(x)); return y;
}
__device__ __forceinline__ float sigf(float x) {
    return rcpf(1.0f + ex2f(-1.4426950408889634f * x));
}
__device__ __forceinline__ float mytanh(float x) {
    return fmaf(2.0f, sigf(2.0f * x), -1.0f);
}

// ---- packed f32x2 helpers ----
__device__ __forceinline__ u64 pk2(float lo, float hi) {
    u64 r; asm("mov.b64 %0, {%1, %2};" : "=l"(r) : "f"(lo), "f"(hi)); return r;
}
__device__ __forceinline__ void upk2(float& lo, float& hi, u64 v) {
    asm("mov.b64 {%0, %1}, %2;" : "=f"(lo), "=f"(hi) : "l"(v));
}
__device__ __forceinline__ u64 ffma2(u64 a, u64 b, u64 c) {
    u64 d; asm("fma.rn.f32x2 %0, %1, %2, %3;" : "=l"(d) : "l"(a), "l"(b), "l"(c)); return d;
}

// ============================================================================
// K1: pre-MLPs + W_ih projection. 1 element/thread, f32x2 accumulators,
// u-phase then x-phase to cap live registers; 2 blocks/SM guaranteed.
// ============================================================================
__global__ void __launch_bounds__(256, 2) k1_gates(
    const float* __restrict__ u_in, const float* __restrict__ x_in,
    const float* __restrict__ pu_W1, const float* __restrict__ pu_b1,
    const float* __restrict__ pu_W2, const float* __restrict__ pu_b2,
    const float* __restrict__ px_W1, const float* __restrict__ px_b1,
    const float* __restrict__ px_W2, const float* __restrict__ px_b2,
    const float* __restrict__ W_ih, const float* __restrict__ b_ih)
{
    __shared__ __align__(16) float s_pu1[64], s_px1[64];       // [c][i]
    __shared__ __align__(16) float s_pu2T[256], s_px2T[256];   // [k][c]
    __shared__ __align__(16) float s_wT[32 * 48];              // [d][g]
    __shared__ __align__(16) float s_bih[48];
    __shared__ __align__(8)  float s_bu1[16], s_bu2[16], s_bx1[16], s_bx2[16];

    const int tid = threadIdx.x;
    for (int i = tid; i < 64;  i += 256) { s_pu1[i] = pu_W1[i]; s_px1[i] = px_W1[i]; }
    for (int i = tid; i < 256; i += 256) {
        s_pu2T[(i & 15) * 16 + (i >> 4)] = pu_W2[i];
        s_px2T[(i & 15) * 16 + (i >> 4)] = px_W2[i];
    }
    for (int i = tid; i < 1536; i += 256) s_wT[(i & 31) * 48 + (i >> 5)] = W_ih[i];
    if (tid < 48) s_bih[tid] = b_ih[tid];
    if (tid < 16) { s_bu1[tid] = pu_b1[tid]; s_bu2[tid] = pu_b2[tid];
                    s_bx1[tid] = px_b1[tid]; s_bx2[tid] = px_b2[tid]; }
    __syncthreads();

    const int e = blockIdx.x * 256 + tid;

    // gate accumulators (48 outputs = 24 f32x2), seeded with b_ih
    u64 acc[24];
#pragma unroll
    for (int j = 0; j < 24; j++) acc[j] = *(const u64*)&s_bih[2 * j];

    // ================= u phase =================
    {
        const float4 u = *(const float4*)(u_in + (size_t)e * 4);
        float t[16];
#pragma unroll
        for (int c = 0; c < 16; c++) {
            const float4 w = *(const float4*)&s_pu1[c * 4];
            t[c] = mytanh(fmaf(w.x, u.x, fmaf(w.y, u.y, fmaf(w.z, u.z, fmaf(w.w, u.w, s_bu1[c])))));
        }
        u64 a8[8];
#pragma unroll
        for (int j = 0; j < 8; j++) a8[j] = *(const u64*)&s_bu2[2 * j];
#pragma unroll
        for (int k = 0; k < 16; k++) {
            const u64 d2 = pk2(t[k], t[k]);
            const ulonglong2* row = (const ulonglong2*)&s_pu2T[k * 16];
#pragma unroll
            for (int q = 0; q < 4; q++) {
                const ulonglong2 w = row[q];
                a8[2*q]   = ffma2(w.x, d2, a8[2*q]);
                a8[2*q+1] = ffma2(w.y, d2, a8[2*q+1]);
            }
        }
        float ue[16];
#pragma unroll
        for (int j = 0; j < 8; j++) upk2(ue[2*j], ue[2*j+1], a8[j]);
#pragma unroll
        for (int c = 0; c < 16; c++) ue[c] = mytanh(ue[c]);
        // gate contribution, k = 0..15
#pragma unroll
        for (int k = 0; k < 16; k++) {
            const u64 a2 = pk2(ue[k], ue[k]);
            const ulonglong2* row = (const ulonglong2*)&s_wT[k * 48];
#pragma unroll
            for (int i = 0; i < 12; i++) {
                const ulonglong2 w = row[i];
                acc[2*i]   = ffma2(w.x, a2, acc[2*i]);
                acc[2*i+1] = ffma2(w.y, a2, acc[2*i+1]);
            }
        }
    }
    // ================= x phase =================
    {
        const float4 x = *(const float4*)(x_in + (size_t)e * 4);
        float t[16];
#pragma unroll
        for (int c = 0; c < 16; c++) {
            const float4 w = *(const float4*)&s_px1[c * 4];
            t[c] = mytanh(fmaf(w.x, x.x, fmaf(w.y, x.y, fmaf(w.z, x.z, fmaf(w.w, x.w, s_bx1[c])))));
        }
        u64 a8[8];
#pragma unroll
        for (int j = 0; j < 8; j++) a8[j] = *(const u64*)&s_bx2[2 * j];
#pragma unroll
        for (int k = 0; k < 16; k++) {
            const u64 d2 = pk2(t[k], t[k]);
            const ulonglong2* row = (const ulonglong2*)&s_px2T[k * 16];
#pragma unroll
            for (int q = 0; q < 4; q++) {
                const ulonglong2 w = row[q];
                a8[2*q]   = ffma2(w.x, d2, a8[2*q]);
                a8[2*q+1] = ffma2(w.y, d2, a8[2*q+1]);
            }
        }
        float xe[16];
#pragma unroll
        for (int j = 0; j < 8; j++) upk2(xe[2*j], xe[2*j+1], a8[j]);
#pragma unroll
        for (int c = 0; c < 16; c++) xe[c] = mytanh(xe[c]);
        // gate contribution, k = 16..31
#pragma unroll
        for (int k = 0; k < 16; k++) {
            const u64 a2 = pk2(xe[k], xe[k]);
            const ulonglong2* row = (const ulonglong2*)&s_wT[(16 + k) * 48];
#pragma unroll
            for (int i = 0; i < 12; i++) {
                const ulonglong2 w = row[i];
                acc[2*i]   = ffma2(w.x, a2, acc[2*i]);
                acc[2*i+1] = ffma2(w.y, a2, acc[2*i+1]);
            }
        }
    }
    float* gp = g_gates + (size_t)e * 48;
#pragma unroll
    for (int i = 0; i < 12; i++)
        ((ulonglong2*)gp)[i] = make_ulonglong2(acc[2*i], acc[2*i+1]);
}

// ============================================================================
// K2: GRU recurrence + fused decoder — ONE WARP PER BATCH ELEMENT.
// Lanes 0-15 ("rz"): r,z dots for channel c=lane. Lanes 16-31 ("n"):
// n dot, h update. Decoder hidden unit = lane id (uniform both halves).
// 8-deep gate prefetch ring; 1 syncwarp/step; decoder after sync so its
// shfl reduction overlaps the next step's LDS.
// ============================================================================
#define WPB 14
#define NT2 (WPB * 32)

__global__ void __launch_bounds__(NT2, 1) k2_recur(
    const float* __restrict__ W_hh, const float* __restrict__ b_hh,
    const float* __restrict__ dec_W1, const float* __restrict__ dec_b1,
    const float* __restrict__ dec_W2, const float* __restrict__ dec_b2,
    float* __restrict__ out_h, float* __restrict__ out_x)
{
    __shared__ __align__(16) float s_h[2][WPB][16];
    const int tid  = threadIdx.x;
    const int lane = tid & 31;
    const int w    = tid >> 5;          // warp slot = element slot in CTA
    const int c    = lane & 15;         // channel
    const bool rz  = (lane < 16);

    const int b = blockIdx.x * WPB + w;
    const bool active = (b < B_);
    const int bb = active ? b : (B_ - 1);

    // W_hh rows (packed k-pairs): A = r-row (rz) / n-row (n-half), B = z-row
    const int rowA = rz ? c : (32 + c);
    const int rowB = 16 + c;
    u64 wA[8], wB[8];
#pragma unroll
    for (int j = 0; j < 8; j++) {
        wA[j] = *(const u64*)&W_hh[rowA * 16 + 2 * j];
        wB[j] = *(const u64*)&W_hh[rowB * 16 + 2 * j];
    }
    const float seedA = b_hh[rowA];
    const float seedB = b_hh[rowB];

    // decoder: lane owns hidden unit `lane`
    u64 wd[8];
#pragma unroll
    for (int j = 0; j < 8; j++) wd[j] = *(const u64*)&dec_W1[lane * 16 + 2 * j];
    const float db1 = dec_b1[lane];
    const float w2a = dec_W2[0 * 32 + lane];
    const float w2b = dec_W2[1 * 32 + lane];
    const float w2c = dec_W2[2 * 32 + lane];
    const float w2d = dec_W2[3 * 32 + lane];
    const float db2 = dec_b2[lane & 3];

    if (lane < 16) { s_h[0][w][c] = 0.f; s_h[1][w][c] = 0.f; }
    __syncthreads();

    const float* gb = g_gates + (size_t)bb * 48;
    const size_t lstride = (size_t)B_ * 48;
    const int offA = rz ? c : (32 + c);  // xr (rz) / xn (n)
    const int offB = 16 + c;             // xz

    float ra[8], rb[8], na[8], nb[8];
#pragma unroll
    for (int j = 0; j < 8; j++) {
        const float* gp = gb + (size_t)j * lstride;
        ra[j] = gp[offA]; rb[j] = gp[offB];
    }

    for (int blk = 0; blk < L_ / 8; blk++) {
#pragma unroll
        for (int j = 0; j < 8; j++) {
            const int l = blk * 8 + j;
            if (blk < L_ / 8 - 1) {
                const float* gp = gb + (size_t)(l + 8) * lstride;
                na[j] = gp[offA]; nb[j] = gp[offB];
            }
            const int p = j & 1;   // == l & 1
            // read h (all lanes need the full 16-vector, packed)
            const ulonglong2* shp = (const ulonglong2*)s_h[p][w];
            const ulonglong2 q0 = shp[0], q1 = shp[1], q2 = shp[2], q3 = shp[3];
            const u64 hh[8] = {q0.x, q0.y, q1.x, q1.y, q2.x, q2.y, q3.x, q3.y};
            const float h_prev = s_h[p][w][c];

            u64 aA = pk2(seedA, 0.f), aB = pk2(seedB, 0.f);
#pragma unroll
            for (int k = 0; k < 8; k++) {
                aA = ffma2(wA[k], hh[k], aA);
                aB = ffma2(wB[k], hh[k], aB);
            }
            float Al, Ah, Bl, Bh;
            upk2(Al, Ah, aA); upk2(Bl, Bh, aB);
            const float dotA = Al + Ah;            // rz: hr | n: hn (bias-seeded)
            const float dotB = Bl + Bh;            // hz (bias-seeded)
            const float pA = ra[j] + dotA;          // rz: a_r | n: garbage
            const float sw = __shfl_xor_sync(0xffffffffu, pA, 16);  // n gets a_r
            const float z = sigf(rb[j] + dotB);
            const float r = sigf(rz ? pA : sw);
            const float nn = mytanh(fmaf(r, dotA, ra[j]));   // valid on n-half
            const float h_new = fmaf(z, h_prev - nn, nn);
            if (!rz) s_h[1 - p][w][c] = h_new;
            __syncwarp();

            // ---- decoder on hh == h_all[l-1] → out_x[l-1]; overlaps next LDS ----
            if (rz && active) out_h[((size_t)l * B_ + bb) * 16 + c] = h_prev;
            u64 aD = pk2(db1, 0.f);
#pragma unroll
            for (int k = 0; k < 8; k++) aD = ffma2(wd[k], hh[k], aD);
            float Dl, Dh; upk2(Dl, Dh, aD);
            const float d = mytanh(Dl + Dh);
            float p0 = d * w2a, p1 = d * w2b, p2 = d * w2c, p3 = d * w2d;
            float q01  = (lane & 1) ? p1 : p0;
            float q01b = (lane & 1) ? p0 : p1;
            q01 += __shfl_xor_sync(0xffffffffu, q01b, 1);
            float q23  = (lane & 1) ? p3 : p2;
            float q23b = (lane & 1) ? p2 : p3;
            q23 += __shfl_xor_sync(0xffffffffu, q23b, 1);
            float qq  = (lane & 2) ? q23 : q01;
            float qqb = (lane & 2) ? q01 : q23;
            qq += __shfl_xor_sync(0xffffffffu, qqb, 2);
            qq += __shfl_xor_sync(0xffffffffu, qq, 4);
            qq += __shfl_xor_sync(0xffffffffu, qq, 8);
            qq += __shfl_xor_sync(0xffffffffu, qq, 16);
            if (l > 0 && active && lane < 4)
                out_x[((size_t)(l - 1) * B_ + bb) * 4 + lane] = qq + db2;
        }
#pragma unroll
        for (int j = 0; j < 8; j++) { ra[j] = na[j]; rb[j] = nb[j]; }
    }

    // ---- tail: decode final hidden (in s_h[0]) → out_x[L-1] ----
    {
        const ulonglong2* shp = (const ulonglong2*)s_h[0][w];
        const ulonglong2 q0 = shp[0], q1 = shp[1], q2 = shp[2], q3 = shp[3];
        const u64 hh[8] = {q0.x, q0.y, q1.x, q1.y, q2.x, q2.y, q3.x, q3.y};
        u64 aD = pk2(db1, 0.f);
#pragma unroll
        for (int k = 0; k < 8; k++) aD = ffma2(wd[k], hh[k], aD);
        float Dl, Dh; upk2(Dl, Dh, aD);
        const float d = mytanh(Dl + Dh);
        float p0 = d * w2a, p1 = d * w2b, p2 = d * w2c, p3 = d * w2d;
        float q01  = (lane & 1) ? p1 : p0;
        float q01b = (lane & 1) ? p0 : p1;
        q01 += __shfl_xor_sync(0xffffffffu, q01b, 1);
        float q23  = (lane & 1) ? p3 : p2;
        float q23b = (lane & 1) ? p2 : p3;
        q23 += __shfl_xor_sync(0xffffffffu, q23b, 1);
        float qq  = (lane & 2) ? q23 : q01;
        float qqb = (lane & 2) ? q01 : q23;
        qq += __shfl_xor_sync(0xffffffffu, qqb, 2);
        qq += __shfl_xor_sync(0xffffffffu, qq, 4);
        qq += __shfl_xor_sync(0xffffffffu, qq, 8);
        qq += __shfl_xor_sync(0xffffffffu, qq, 16);
        if (active && lane < 4)
            out_x[((size_t)(L_ - 1) * B_ + bb) * 4 + lane] = qq + db2;
    }
}

// ============================================================================
extern "C" void kernel_launch(void* const* d_in, const int* in_sizes, int n_in,
                              void* d_out, int out_size) {
    const float* u_in   = (const float*)d_in[0];
    const float* x_in   = (const float*)d_in[1];
    const float* pu_W1  = (const float*)d_in[2];
    const float* pu_b1  = (const float*)d_in[3];
    const float* pu_W2  = (const float*)d_in[4];
    const float* pu_b2  = (const float*)d_in[5];
    const float* px_W1  = (const float*)d_in[6];
    const float* px_b1  = (const float*)d_in[7];
    const float* px_W2  = (const float*)d_in[8];
    const float* px_b2  = (const float*)d_in[9];
    const float* W_ih   = (const float*)d_in[10];
    const float* b_ih   = (const float*)d_in[11];
    const float* W_hh   = (const float*)d_in[12];
    const float* b_hh   = (const float*)d_in[13];
    const float* dec_W1 = (const float*)d_in[14];
    const float* dec_b1 = (const float*)d_in[15];
    const float* dec_W2 = (const float*)d_in[16];
    const float* dec_b2 = (const float*)d_in[17];

    float* out_x = (float*)d_out;                          // [L,B,4]
    float* out_h = (float*)d_out + (size_t)L_ * B_ * 4;    // [L,B,16]

    k1_gates<<<NE / 256, 256>>>(u_in, x_in, pu_W1, pu_b1, pu_W2, pu_b2,
                                px_W1, px_b1, px_W2, px_b2, W_ih, b_ih);
    k2_recur<<<(B_ + WPB - 1) / WPB, NT2>>>(W_hh, b_hh,
                                            dec_W1, dec_b1, dec_W2, dec_b2,
                                            out_h, out_x);
}

// round 6
// speedup vs baseline: 1.2649x; 1.2649x over previous
#include <cuda_runtime.h>
#include <cstdint>

typedef unsigned long long u64;

#define L_ 1024
#define B_ 2048
#define NE (L_ * B_)

// scratch: input-to-hidden gate projections [L*B][48]
__device__ float g_gates[(size_t)NE * 48];

__device__ __forceinline__ float ex2f(float x) {
    float y; asm("ex2.approx.f32 %0, %1;" : "=f"(y) : "f"(x)); return y;
}
__device__ __forceinline__ float rcpf(float x) {
    float y; asm("rcp.approx.f32 %0, %1;" : "=f"(y) : "f"(x)); return y;
}
__device__ __forceinline__ float sigf(float x) {
    return rcpf(1.0f + ex2f(-1.4426950408889634f * x));
}
__device__ __forceinline__ float mytanh(float x) {
    return fmaf(2.0f, sigf(2.0f * x), -1.0f);
}

// ---- packed f32x2 helpers ----
__device__ __forceinline__ u64 pk2(float lo, float hi) {
    u64 r; asm("mov.b64 %0, {%1, %2};" : "=l"(r) : "f"(lo), "f"(hi)); return r;
}
__device__ __forceinline__ void upk2(float& lo, float& hi, u64 v) {
    asm("mov.b64 {%0, %1}, %2;" : "=f"(lo), "=f"(hi) : "l"(v));
}
__device__ __forceinline__ u64 ffma2(u64 a, u64 b, u64 c) {
    u64 d; asm("fma.rn.f32x2 %0, %1, %2, %3;" : "=l"(d) : "l"(a), "l"(b), "l"(c)); return d;
}
__device__ __forceinline__ u64 fmul2(u64 a, u64 b) {
    u64 d; asm("mul.rn.f32x2 %0, %1, %2;" : "=l"(d) : "l"(a), "l"(b)); return d;
}
__device__ __forceinline__ unsigned cvt_tf32(float f) {
    unsigned r; asm("cvt.rna.tf32.f32 %0, %1;" : "=r"(r) : "f"(f)); return r;
}
__device__ __forceinline__ void mma_tf32(float* c, const unsigned* a, unsigned b0, unsigned b1) {
    asm volatile(
        "mma.sync.aligned.m16n8k8.row.col.f32.tf32.tf32.f32 "
        "{%0,%1,%2,%3}, {%4,%5,%6,%7}, {%8,%9}, {%0,%1,%2,%3};"
        : "+f"(c[0]), "+f"(c[1]), "+f"(c[2]), "+f"(c[3])
        : "r"(a[0]), "r"(a[1]), "r"(a[2]), "r"(a[3]), "r"(b0), "r"(b1));
}

// ============================================================================
// K1: preprocess MLPs in fp32 CUDA cores, gate GEMM (48x32 @ 32xNE) on
// tensor cores (tf32 mma.sync, fp32 accumulate). Warp computes 32 elements'
// embeddings, stages them tf32 in SMEM (stride-36, conflict-free), then
// 3x4x4 = 48 HMMAs produce the 48 gate pre-activations.
// ============================================================================
#define K1T 128
#define EMB_STRIDE 36

__global__ void __launch_bounds__(K1T, 3) k1_gates(
    const float* __restrict__ u_in, const float* __restrict__ x_in,
    const float* __restrict__ pu_W1, const float* __restrict__ pu_b1,
    const float* __restrict__ pu_W2, const float* __restrict__ pu_b2,
    const float* __restrict__ px_W1, const float* __restrict__ px_b1,
    const float* __restrict__ px_W2, const float* __restrict__ px_b2,
    const float* __restrict__ W_ih, const float* __restrict__ b_ih)
{
    __shared__ __align__(16) float s_pu1[64], s_px1[64];       // [c][i]
    __shared__ __align__(16) float s_pu2T[256], s_px2T[256];   // [k][c]
    __shared__ __align__(8)  float s_bu1[16], s_bu2[16], s_bx1[16], s_bx2[16];
    __shared__ unsigned s_emb[4][32 * EMB_STRIDE];             // per-warp [k][e] tf32

    const int tid  = threadIdx.x;
    const int lane = tid & 31;
    const int w    = tid >> 5;

    for (int i = tid; i < 64;  i += K1T) { s_pu1[i] = pu_W1[i]; s_px1[i] = px_W1[i]; }
    for (int i = tid; i < 256; i += K1T) {
        s_pu2T[(i & 15) * 16 + (i >> 4)] = pu_W2[i];
        s_px2T[(i & 15) * 16 + (i >> 4)] = px_W2[i];
    }
    if (tid < 16) { s_bu1[tid] = pu_b1[tid]; s_bu2[tid] = pu_b2[tid];
                    s_bx1[tid] = px_b1[tid]; s_bx2[tid] = px_b2[tid]; }

    // A fragments: W_ih [48][32] row-major, tf32.  a0:(r,c) a1:(r+8,c) a2:(r,c+4) a3:(r+8,c+4)
    const int gq = lane >> 2, tq = lane & 3;
    unsigned af[3][4][4];
    float bih0[3], bih8[3];
#pragma unroll
    for (int mt = 0; mt < 3; mt++) {
        const int r0 = mt * 16 + gq;
#pragma unroll
        for (int kt = 0; kt < 4; kt++) {
            const int c0 = kt * 8 + tq;
            af[mt][kt][0] = cvt_tf32(W_ih[r0 * 32 + c0]);
            af[mt][kt][1] = cvt_tf32(W_ih[(r0 + 8) * 32 + c0]);
            af[mt][kt][2] = cvt_tf32(W_ih[r0 * 32 + c0 + 4]);
            af[mt][kt][3] = cvt_tf32(W_ih[(r0 + 8) * 32 + c0 + 4]);
        }
        bih0[mt] = b_ih[r0];
        bih8[mt] = b_ih[r0 + 8];
    }
    __syncthreads();

    const int e = blockIdx.x * K1T + tid;   // NE divisible by K1T

    // ---- preprocess (fp32, f32x2 accums) ----
    float ue[16], xe[16];
    {
        const float4 u = *(const float4*)(u_in + (size_t)e * 4);
        float t[16];
#pragma unroll
        for (int c = 0; c < 16; c++) {
            const float4 wt = *(const float4*)&s_pu1[c * 4];
            t[c] = mytanh(fmaf(wt.x, u.x, fmaf(wt.y, u.y, fmaf(wt.z, u.z, fmaf(wt.w, u.w, s_bu1[c])))));
        }
        u64 a8[8];
#pragma unroll
        for (int j = 0; j < 8; j++) a8[j] = *(const u64*)&s_bu2[2 * j];
#pragma unroll
        for (int k = 0; k < 16; k++) {
            const u64 d2 = pk2(t[k], t[k]);
            const ulonglong2* row = (const ulonglong2*)&s_pu2T[k * 16];
#pragma unroll
            for (int q = 0; q < 4; q++) {
                const ulonglong2 wv = row[q];
                a8[2*q]   = ffma2(wv.x, d2, a8[2*q]);
                a8[2*q+1] = ffma2(wv.y, d2, a8[2*q+1]);
            }
        }
#pragma unroll
        for (int j = 0; j < 8; j++) upk2(ue[2*j], ue[2*j+1], a8[j]);
#pragma unroll
        for (int c = 0; c < 16; c++) ue[c] = mytanh(ue[c]);
    }
    {
        const float4 x = *(const float4*)(x_in + (size_t)e * 4);
        float t[16];
#pragma unroll
        for (int c = 0; c < 16; c++) {
            const float4 wt = *(const float4*)&s_px1[c * 4];
            t[c] = mytanh(fmaf(wt.x, x.x, fmaf(wt.y, x.y, fmaf(wt.z, x.z, fmaf(wt.w, x.w, s_bx1[c])))));
        }
        u64 a8[8];
#pragma unroll
        for (int j = 0; j < 8; j++) a8[j] = *(const u64*)&s_bx2[2 * j];
#pragma unroll
        for (int k = 0; k < 16; k++) {
            const u64 d2 = pk2(t[k], t[k]);
            const ulonglong2* row = (const ulonglong2*)&s_px2T[k * 16];
#pragma unroll
            for (int q = 0; q < 4; q++) {
                const ulonglong2 wv = row[q];
                a8[2*q]   = ffma2(wv.x, d2, a8[2*q]);
                a8[2*q+1] = ffma2(wv.y, d2, a8[2*q+1]);
            }
        }
#pragma unroll
        for (int j = 0; j < 8; j++) upk2(xe[2*j], xe[2*j+1], a8[j]);
#pragma unroll
        for (int c = 0; c < 16; c++) xe[c] = mytanh(xe[c]);
    }

    // ---- stage embeddings tf32 into SMEM [k][e], k = 0..15 u, 16..31 x ----
    unsigned* se = s_emb[w];
#pragma unroll
    for (int c = 0; c < 16; c++) {
        se[c * EMB_STRIDE + lane]        = cvt_tf32(ue[c]);
        se[(16 + c) * EMB_STRIDE + lane] = cvt_tf32(xe[c]);
    }
    __syncwarp();

    // ---- gate GEMM: D[48 x 32] = W_ih @ emb  (+ b_ih), tf32 HMMA ----
    const int warp_e0 = blockIdx.x * K1T + w * 32;
#pragma unroll
    for (int mt = 0; mt < 3; mt++) {
#pragma unroll
        for (int nt = 0; nt < 4; nt++) {
            float c[4] = {bih0[mt], bih0[mt], bih8[mt], bih8[mt]};
#pragma unroll
            for (int kt = 0; kt < 4; kt++) {
                const unsigned b0 = se[(kt * 8 + tq) * EMB_STRIDE + nt * 8 + gq];
                const unsigned b1 = se[(kt * 8 + 4 + tq) * EMB_STRIDE + nt * 8 + gq];
                mma_tf32(c, af[mt][kt], b0, b1);
            }
            const int eb = warp_e0 + nt * 8 + tq * 2;
            const int g0 = mt * 16 + gq;
            g_gates[(size_t)eb * 48 + g0]           = c[0];
            g_gates[(size_t)(eb + 1) * 48 + g0]     = c[1];
            g_gates[(size_t)eb * 48 + g0 + 8]       = c[2];
            g_gates[(size_t)(eb + 1) * 48 + g0 + 8] = c[3];
        }
    }
}

// ============================================================================
// K2: GRU recurrence + fused decoder (R4 layout: 16 lanes/element, 2 elems
// per warp). 8-deep gate prefetch ring, f32x2 dots, decoder off critical path.
// ============================================================================
#define BPC 14
#define NT2 (BPC * 16)

__global__ void __launch_bounds__(NT2, 1) k2_recur(
    const float* __restrict__ W_hh, const float* __restrict__ b_hh,
    const float* __restrict__ dec_W1, const float* __restrict__ dec_b1,
    const float* __restrict__ dec_W2, const float* __restrict__ dec_b2,
    float* __restrict__ out_h, float* __restrict__ out_x)
{
    __shared__ __align__(16) float s_h[2][BPC][16];
    const int tid = threadIdx.x, lane = tid & 15, g = tid >> 4;
    const int b = blockIdx.x * BPC + g;
    const bool active = (b < B_);
    const int bb = active ? b : (B_ - 1);

    u64 vrp[8], vzp[8], vnp[8];
#pragma unroll
    for (int j = 0; j < 8; j++) {
        vrp[j] = *(const u64*)&W_hh[lane * 16 + 2 * j];
        vzp[j] = *(const u64*)&W_hh[(16 + lane) * 16 + 2 * j];
        vnp[j] = *(const u64*)&W_hh[(32 + lane) * 16 + 2 * j];
    }
    const float bhr = b_hh[lane], bhz = b_hh[16 + lane], bhn = b_hh[32 + lane];

    u64 wd0[8], wd1[8];
#pragma unroll
    for (int j = 0; j < 8; j++) {
        wd0[j] = *(const u64*)&dec_W1[(2 * lane) * 16 + 2 * j];
        wd1[j] = *(const u64*)&dec_W1[(2 * lane + 1) * 16 + 2 * j];
    }
    const float db1_0 = dec_b1[2 * lane], db1_1 = dec_b1[2 * lane + 1];
    u64 w2p[4];
#pragma unroll
    for (int o = 0; o < 4; o++) w2p[o] = *(const u64*)&dec_W2[o * 32 + 2 * lane];
    const float db2 = dec_b2[lane & 3];

    s_h[0][g][lane] = 0.f;
    s_h[1][g][lane] = 0.f;
    __syncthreads();

    const float* gb = g_gates + (size_t)bb * 48;
    const size_t lstride = (size_t)B_ * 48;

    float cr[8], cz[8], cn[8], nr[8], nz[8], nn_[8];
#pragma unroll
    for (int j = 0; j < 8; j++) {
        const float* gp = gb + (size_t)j * lstride;
        cr[j] = gp[lane]; cz[j] = gp[16 + lane]; cn[j] = gp[32 + lane];
    }

    for (int blk = 0; blk < L_ / 8; blk++) {
#pragma unroll
        for (int j = 0; j < 8; j++) {
            const int l = blk * 8 + j;
            if (blk < L_ / 8 - 1) {
                const float* gp = gb + (size_t)(l + 8) * lstride;
                nr[j] = gp[lane]; nz[j] = gp[16 + lane]; nn_[j] = gp[32 + lane];
            }
            const int p = j & 1;
            const ulonglong2* sh = (const ulonglong2*)s_h[p][g];
            const ulonglong2 q0 = sh[0], q1 = sh[1], q2 = sh[2], q3 = sh[3];
            const u64 hhp[8] = {q0.x, q0.y, q1.x, q1.y, q2.x, q2.y, q3.x, q3.y};
            const float h_prev = s_h[p][g][lane];
            if (active) out_h[((size_t)l * B_ + bb) * 16 + lane] = h_prev;

            u64 ar = pk2(bhr, 0.f), az = pk2(bhz, 0.f), an = pk2(bhn, 0.f);
#pragma unroll
            for (int k = 0; k < 8; k++) {
                ar = ffma2(vrp[k], hhp[k], ar);
                az = ffma2(vzp[k], hhp[k], az);
                an = ffma2(vnp[k], hhp[k], an);
            }
            float rl, rh, zl, zh, nl, nh;
            upk2(rl, rh, ar); upk2(zl, zh, az); upk2(nl, nh, an);
            const float r = sigf(cr[j] + (rl + rh));
            const float z = sigf(cz[j] + (zl + zh));
            const float n = mytanh(fmaf(r, nl + nh, cn[j]));
            const float h_new = fmaf(z, h_prev - n, n);
            s_h[1 - p][g][lane] = h_new;

            // decoder on hhp == h_all[l-1] → out_x[l-1]
            u64 aD0 = pk2(db1_0, 0.f), aD1 = pk2(db1_1, 0.f);
#pragma unroll
            for (int k = 0; k < 8; k++) {
                aD0 = ffma2(wd0[k], hhp[k], aD0);
                aD1 = ffma2(wd1[k], hhp[k], aD1);
            }
            float d0l, d0h, d1l, d1h;
            upk2(d0l, d0h, aD0); upk2(d1l, d1h, aD1);
            const float d0 = mytanh(d0l + d0h);
            const float d1 = mytanh(d1l + d1h);
            const u64 dpk = pk2(d0, d1);
            float pp0, pp1, pp2, pp3;
            { float lo, hi;
              upk2(lo, hi, fmul2(w2p[0], dpk)); pp0 = lo + hi;
              upk2(lo, hi, fmul2(w2p[1], dpk)); pp1 = lo + hi;
              upk2(lo, hi, fmul2(w2p[2], dpk)); pp2 = lo + hi;
              upk2(lo, hi, fmul2(w2p[3], dpk)); pp3 = lo + hi; }
            float q01  = (lane & 1) ? pp1 : pp0;
            float q01b = (lane & 1) ? pp0 : pp1;
            q01 += __shfl_xor_sync(0xffffffffu, q01b, 1);
            float q23  = (lane & 1) ? pp3 : pp2;
            float q23b = (lane & 1) ? pp2 : pp3;
            q23 += __shfl_xor_sync(0xffffffffu, q23b, 1);
            float qq  = (lane & 2) ? q23 : q01;
            float qqb = (lane & 2) ? q01 : q23;
            qq += __shfl_xor_sync(0xffffffffu, qqb, 2);
            qq += __shfl_xor_sync(0xffffffffu, qq, 4);
            qq += __shfl_xor_sync(0xffffffffu, qq, 8);
            if (l > 0 && active && lane < 4)
                out_x[((size_t)(l - 1) * B_ + bb) * 4 + lane] = qq + db2;

            __syncwarp();
        }
#pragma unroll
        for (int j = 0; j < 8; j++) { cr[j] = nr[j]; cz[j] = nz[j]; cn[j] = nn_[j]; }
    }

    // tail: decode final hidden (in s_h[0]) → out_x[L-1]
    {
        const ulonglong2* sh = (const ulonglong2*)s_h[0][g];
        const ulonglong2 q0 = sh[0], q1 = sh[1], q2 = sh[2], q3 = sh[3];
        const u64 hhp[8] = {q0.x, q0.y, q1.x, q1.y, q2.x, q2.y, q3.x, q3.y};
        u64 aD0 = pk2(db1_0, 0.f), aD1 = pk2(db1_1, 0.f);
#pragma unroll
        for (int k = 0; k < 8; k++) {
            aD0 = ffma2(wd0[k], hhp[k], aD0);
            aD1 = ffma2(wd1[k], hhp[k], aD1);
        }
        float d0l, d0h, d1l, d1h;
        upk2(d0l, d0h, aD0); upk2(d1l, d1h, aD1);
        const float d0 = mytanh(d0l + d0h);
        const float d1 = mytanh(d1l + d1h);
        const u64 dpk = pk2(d0, d1);
        float pp0, pp1, pp2, pp3;
        { float lo, hi;
          upk2(lo, hi, fmul2(w2p[0], dpk)); pp0 = lo + hi;
          upk2(lo, hi, fmul2(w2p[1], dpk)); pp1 = lo + hi;
          upk2(lo, hi, fmul2(w2p[2], dpk)); pp2 = lo + hi;
          upk2(lo, hi, fmul2(w2p[3], dpk)); pp3 = lo + hi; }
        float q01  = (lane & 1) ? pp1 : pp0;
        float q01b = (lane & 1) ? pp0 : pp1;
        q01 += __shfl_xor_sync(0xffffffffu, q01b, 1);
        float q23  = (lane & 1) ? pp3 : pp2;
        float q23b = (lane & 1) ? pp2 : pp3;
        q23 += __shfl_xor_sync(0xffffffffu, q23b, 1);
        float qq  = (lane & 2) ? q23 : q01;
        float qqb = (lane & 2) ? q01 : q23;
        qq += __shfl_xor_sync(0xffffffffu, qqb, 2);
        qq += __shfl_xor_sync(0xffffffffu, qq, 4);
        qq += __shfl_xor_sync(0xffffffffu, qq, 8);
        if (active && lane < 4)
            out_x[((size_t)(L_ - 1) * B_ + bb) * 4 + lane] = qq + db2;
    }
}

// ============================================================================
extern "C" void kernel_launch(void* const* d_in, const int* in_sizes, int n_in,
                              void* d_out, int out_size) {
    const float* u_in   = (const float*)d_in[0];
    const float* x_in   = (const float*)d_in[1];
    const float* pu_W1  = (const float*)d_in[2];
    const float* pu_b1  = (const float*)d_in[3];
    const float* pu_W2  = (const float*)d_in[4];
    const float* pu_b2  = (const float*)d_in[5];
    const float* px_W1  = (const float*)d_in[6];
    const float* px_b1  = (const float*)d_in[7];
    const float* px_W2  = (const float*)d_in[8];
    const float* px_b2  = (const float*)d_in[9];
    const float* W_ih   = (const float*)d_in[10];
    const float* b_ih   = (const float*)d_in[11];
    const float* W_hh   = (const float*)d_in[12];
    const float* b_hh   = (const float*)d_in[13];
    const float* dec_W1 = (const float*)d_in[14];
    const float* dec_b1 = (const float*)d_in[15];
    const float* dec_W2 = (const float*)d_in[16];
    const float* dec_b2 = (const float*)d_in[17];

    float* out_x = (float*)d_out;                          // [L,B,4]
    float* out_h = (float*)d_out + (size_t)L_ * B_ * 4;    // [L,B,16]

    k1_gates<<<NE / K1T, K1T>>>(u_in, x_in, pu_W1, pu_b1, pu_W2, pu_b2,
                                px_W1, px_b1, px_W2, px_b2, W_ih, b_ih);
    k2_recur<<<(B_ + BPC - 1) / BPC, NT2>>>(W_hh, b_hh,
                                            dec_W1, dec_b1, dec_W2, dec_b2,
                                            out_h, out_x);
}

// round 7
// speedup vs baseline: 1.2859x; 1.0166x over previous
#include <cuda_runtime.h>
#include <cstdint>

typedef unsigned long long u64;

#define L_ 1024
#define B_ 2048
#define NE (L_ * B_)

// scratch: gate pre-activations in HMMA fragment-tile layout:
// tile t = (l*256 + b/8), gate-block mt = g/16 → 128-float tile in fragment order
//   offset(r = g%16, c = b%8) = (r&7)*16 + (c>>1)*4 + ((r>>3)<<1) + (c&1)
__device__ float g_gates[(size_t)NE * 48];

__device__ __forceinline__ float ex2f(float x) {
    float y; asm("ex2.approx.f32 %0, %1;" : "=f"(y) : "f"(x)); return y;
}
__device__ __forceinline__ float rcpf(float x) {
    float y; asm("rcp.approx.f32 %0, %1;" : "=f"(y) : "f"(x)); return y;
}
__device__ __forceinline__ float sigf(float x) {
    return rcpf(1.0f + ex2f(-1.4426950408889634f * x));
}
__device__ __forceinline__ float mytanh(float x) {
    return fmaf(2.0f, sigf(2.0f * x), -1.0f);
}

// ---- packed f32x2 helpers ----
__device__ __forceinline__ u64 pk2(float lo, float hi) {
    u64 r; asm("mov.b64 %0, {%1, %2};" : "=l"(r) : "f"(lo), "f"(hi)); return r;
}
__device__ __forceinline__ void upk2(float& lo, float& hi, u64 v) {
    asm("mov.b64 {%0, %1}, %2;" : "=f"(lo), "=f"(hi) : "l"(v));
}
__device__ __forceinline__ u64 ffma2(u64 a, u64 b, u64 c) {
    u64 d; asm("fma.rn.f32x2 %0, %1, %2, %3;" : "=l"(d) : "l"(a), "l"(b), "l"(c)); return d;
}
__device__ __forceinline__ u64 fmul2(u64 a, u64 b) {
    u64 d; asm("mul.rn.f32x2 %0, %1, %2;" : "=l"(d) : "l"(a), "l"(b)); return d;
}
__device__ __forceinline__ unsigned cvt_tf32(float f) {
    unsigned r; asm("cvt.rna.tf32.f32 %0, %1;" : "=r"(r) : "f"(f)); return r;
}
__device__ __forceinline__ void mma_tf32(float* c, const unsigned* a, unsigned b0, unsigned b1) {
    asm volatile(
        "mma.sync.aligned.m16n8k8.row.col.f32.tf32.tf32.f32 "
        "{%0,%1,%2,%3}, {%4,%5,%6,%7}, {%8,%9}, {%0,%1,%2,%3};"
        : "+f"(c[0]), "+f"(c[1]), "+f"(c[2]), "+f"(c[3])
        : "r"(a[0]), "r"(a[1]), "r"(a[2]), "r"(a[3]), "r"(b0), "r"(b1));
}

// ============================================================================
// K1: preprocess MLPs (fp32) + gate GEMM on tensor cores; fragments stored
// DIRECTLY to g_gates in fragment-tile layout via coalesced STG.128.
// ============================================================================
#define K1T 128
#define EMB_STRIDE 36

__global__ void __launch_bounds__(K1T, 3) k1_gates(
    const float* __restrict__ u_in, const float* __restrict__ x_in,
    const float* __restrict__ pu_W1, const float* __restrict__ pu_b1,
    const float* __restrict__ pu_W2, const float* __restrict__ pu_b2,
    const float* __restrict__ px_W1, const float* __restrict__ px_b1,
    const float* __restrict__ px_W2, const float* __restrict__ px_b2,
    const float* __restrict__ W_ih, const float* __restrict__ b_ih)
{
    __shared__ __align__(16) float s_pu1[64], s_px1[64];       // [c][i]
    __shared__ __align__(16) float s_pu2T[256], s_px2T[256];   // [k][c]
    __shared__ __align__(8)  float s_bu1[16], s_bu2[16], s_bx1[16], s_bx2[16];
    __shared__ unsigned s_emb[4][32 * EMB_STRIDE];             // per-warp [k][e] tf32

    const int tid  = threadIdx.x;
    const int lane = tid & 31;
    const int w    = tid >> 5;

    for (int i = tid; i < 64;  i += K1T) { s_pu1[i] = pu_W1[i]; s_px1[i] = px_W1[i]; }
    for (int i = tid; i < 256; i += K1T) {
        s_pu2T[(i & 15) * 16 + (i >> 4)] = pu_W2[i];
        s_px2T[(i & 15) * 16 + (i >> 4)] = px_W2[i];
    }
    if (tid < 16) { s_bu1[tid] = pu_b1[tid]; s_bu2[tid] = pu_b2[tid];
                    s_bx1[tid] = px_b1[tid]; s_bx2[tid] = px_b2[tid]; }

    // A fragments: W_ih [48][32] row-major, tf32
    const int gq = lane >> 2, tq = lane & 3;
    unsigned af[3][4][4];
    float bih0[3], bih8[3];
#pragma unroll
    for (int mt = 0; mt < 3; mt++) {
        const int r0 = mt * 16 + gq;
#pragma unroll
        for (int kt = 0; kt < 4; kt++) {
            const int c0 = kt * 8 + tq;
            af[mt][kt][0] = cvt_tf32(W_ih[r0 * 32 + c0]);
            af[mt][kt][1] = cvt_tf32(W_ih[(r0 + 8) * 32 + c0]);
            af[mt][kt][2] = cvt_tf32(W_ih[r0 * 32 + c0 + 4]);
            af[mt][kt][3] = cvt_tf32(W_ih[(r0 + 8) * 32 + c0 + 4]);
        }
        bih0[mt] = b_ih[r0];
        bih8[mt] = b_ih[r0 + 8];
    }
    __syncthreads();

    const int e = blockIdx.x * K1T + tid;   // NE divisible by K1T

    // ---- preprocess (fp32, f32x2 accums) ----
    float ue[16], xe[16];
    {
        const float4 u = *(const float4*)(u_in + (size_t)e * 4);
        float t[16];
#pragma unroll
        for (int c = 0; c < 16; c++) {
            const float4 wt = *(const float4*)&s_pu1[c * 4];
            t[c] = mytanh(fmaf(wt.x, u.x, fmaf(wt.y, u.y, fmaf(wt.z, u.z, fmaf(wt.w, u.w, s_bu1[c])))));
        }
        u64 a8[8];
#pragma unroll
        for (int j = 0; j < 8; j++) a8[j] = *(const u64*)&s_bu2[2 * j];
#pragma unroll
        for (int k = 0; k < 16; k++) {
            const u64 d2 = pk2(t[k], t[k]);
            const ulonglong2* row = (const ulonglong2*)&s_pu2T[k * 16];
#pragma unroll
            for (int q = 0; q < 4; q++) {
                const ulonglong2 wv = row[q];
                a8[2*q]   = ffma2(wv.x, d2, a8[2*q]);
                a8[2*q+1] = ffma2(wv.y, d2, a8[2*q+1]);
            }
        }
#pragma unroll
        for (int j = 0; j < 8; j++) upk2(ue[2*j], ue[2*j+1], a8[j]);
#pragma unroll
        for (int c = 0; c < 16; c++) ue[c] = mytanh(ue[c]);
    }
    {
        const float4 x = *(const float4*)(x_in + (size_t)e * 4);
        float t[16];
#pragma unroll
        for (int c = 0; c < 16; c++) {
            const float4 wt = *(const float4*)&s_px1[c * 4];
            t[c] = mytanh(fmaf(wt.x, x.x, fmaf(wt.y, x.y, fmaf(wt.z, x.z, fmaf(wt.w, x.w, s_bx1[c])))));
        }
        u64 a8[8];
#pragma unroll
        for (int j = 0; j < 8; j++) a8[j] = *(const u64*)&s_bx2[2 * j];
#pragma unroll
        for (int k = 0; k < 16; k++) {
            const u64 d2 = pk2(t[k], t[k]);
            const ulonglong2* row = (const ulonglong2*)&s_px2T[k * 16];
#pragma unroll
            for (int q = 0; q < 4; q++) {
                const ulonglong2 wv = row[q];
                a8[2*q]   = ffma2(wv.x, d2, a8[2*q]);
                a8[2*q+1] = ffma2(wv.y, d2, a8[2*q+1]);
            }
        }
#pragma unroll
        for (int j = 0; j < 8; j++) upk2(xe[2*j], xe[2*j+1], a8[j]);
#pragma unroll
        for (int c = 0; c < 16; c++) xe[c] = mytanh(xe[c]);
    }

    // ---- stage embeddings tf32 into SMEM [k][e] ----
    unsigned* se = s_emb[w];
#pragma unroll
    for (int c = 0; c < 16; c++) {
        se[c * EMB_STRIDE + lane]        = cvt_tf32(ue[c]);
        se[(16 + c) * EMB_STRIDE + lane] = cvt_tf32(xe[c]);
    }
    __syncwarp();

    // ---- gate GEMM; store fragments directly (coalesced STG.128) ----
    const int tg0 = (blockIdx.x * K1T + w * 32) >> 3;   // first element-octet tile
#pragma unroll
    for (int mt = 0; mt < 3; mt++) {
#pragma unroll
        for (int nt = 0; nt < 4; nt++) {
            float c[4] = {bih0[mt], bih0[mt], bih8[mt], bih8[mt]};
#pragma unroll
            for (int kt = 0; kt < 4; kt++) {
                const unsigned b0 = se[(kt * 8 + tq) * EMB_STRIDE + nt * 8 + gq];
                const unsigned b1 = se[(kt * 8 + 4 + tq) * EMB_STRIDE + nt * 8 + gq];
                mma_tf32(c, af[mt][kt], b0, b1);
            }
            float4* dst = (float4*)(g_gates + ((size_t)(tg0 + nt) * 3 + mt) * 128);
            dst[lane] = make_float4(c[0], c[1], c[2], c[3]);
        }
    }
}

// ============================================================================
// K2: GRU recurrence + fused decoder. syncwarp right after h store; decoder
// (dots + tanh + shfl reduction) runs after it on register copies, so its
// long latency overlaps the next step's loads/dots.
// ============================================================================
#define BPC 14
#define NT2 (BPC * 16)
#define TILE_STRIDE_L ((B_ / 8) * 384)   // floats per l-step in g_gates

__global__ void __launch_bounds__(NT2, 1) k2_recur(
    const float* __restrict__ W_hh, const float* __restrict__ b_hh,
    const float* __restrict__ dec_W1, const float* __restrict__ dec_b1,
    const float* __restrict__ dec_W2, const float* __restrict__ dec_b2,
    float* __restrict__ out_h, float* __restrict__ out_x)
{
    __shared__ __align__(16) float s_h[2][BPC][16];
    const int tid = threadIdx.x, lane = tid & 15, g = tid >> 4;
    const int b = blockIdx.x * BPC + g;
    const bool active = (b < B_);
    const int bb = active ? b : (B_ - 1);

    u64 vrp[8], vzp[8], vnp[8];
#pragma unroll
    for (int j = 0; j < 8; j++) {
        vrp[j] = *(const u64*)&W_hh[lane * 16 + 2 * j];
        vzp[j] = *(const u64*)&W_hh[(16 + lane) * 16 + 2 * j];
        vnp[j] = *(const u64*)&W_hh[(32 + lane) * 16 + 2 * j];
    }
    const float bhr = b_hh[lane], bhz = b_hh[16 + lane], bhn = b_hh[32 + lane];

    u64 wd0[8], wd1[8];
#pragma unroll
    for (int j = 0; j < 8; j++) {
        wd0[j] = *(const u64*)&dec_W1[(2 * lane) * 16 + 2 * j];
        wd1[j] = *(const u64*)&dec_W1[(2 * lane + 1) * 16 + 2 * j];
    }
    const float db1_0 = dec_b1[2 * lane], db1_1 = dec_b1[2 * lane + 1];
    u64 w2p[4];
#pragma unroll
    for (int o = 0; o < 4; o++) w2p[o] = *(const u64*)&dec_W2[o * 32 + 2 * lane];
    const float db2 = dec_b2[lane & 3];

    s_h[0][g][lane] = 0.f;
    s_h[1][g][lane] = 0.f;
    __syncthreads();

    // fragment-layout gate addressing (loop-invariant offset)
    const int cc = bb & 7;
    const int off = (lane & 7) * 16 + ((cc >> 1) << 2) + ((lane >> 3) << 1) + (cc & 1);
    const float* gb = g_gates + (size_t)(bb >> 3) * 384 + off;

    float cr[8], cz[8], cn[8], nr[8], nz[8], nn_[8];
#pragma unroll
    for (int j = 0; j < 8; j++) {
        const float* gp = gb + (size_t)j * TILE_STRIDE_L;
        cr[j] = gp[0]; cz[j] = gp[128]; cn[j] = gp[256];
    }

    for (int blk = 0; blk < L_ / 8; blk++) {
#pragma unroll
        for (int j = 0; j < 8; j++) {
            const int l = blk * 8 + j;
            if (blk < L_ / 8 - 1) {
                const float* gp = gb + (size_t)(l + 8) * TILE_STRIDE_L;
                nr[j] = gp[0]; nz[j] = gp[128]; nn_[j] = gp[256];
            }
            const int p = j & 1;
            const ulonglong2* sh = (const ulonglong2*)s_h[p][g];
            const ulonglong2 q0 = sh[0], q1 = sh[1], q2 = sh[2], q3 = sh[3];
            const u64 hhp[8] = {q0.x, q0.y, q1.x, q1.y, q2.x, q2.y, q3.x, q3.y};
            const float h_prev = s_h[p][g][lane];
            if (active) out_h[((size_t)l * B_ + bb) * 16 + lane] = h_prev;

            // ---- recurrence (critical path) ----
            u64 ar = pk2(bhr, 0.f), az = pk2(bhz, 0.f), an = pk2(bhn, 0.f);
#pragma unroll
            for (int k = 0; k < 8; k++) {
                ar = ffma2(vrp[k], hhp[k], ar);
                az = ffma2(vzp[k], hhp[k], az);
                an = ffma2(vnp[k], hhp[k], an);
            }
            float rl, rh, zl, zh, nl, nh;
            upk2(rl, rh, ar); upk2(zl, zh, az); upk2(nl, nh, an);
            const float r = sigf(cr[j] + (rl + rh));
            const float z = sigf(cz[j] + (zl + zh));
            const float n = mytanh(fmaf(r, nl + nh, cn[j]));
            const float h_new = fmaf(z, h_prev - n, n);
            s_h[1 - p][g][lane] = h_new;
            __syncwarp();   // release next step immediately

            // ---- decoder on register copy hhp == h_all[l-1] → out_x[l-1] ----
            u64 aD0 = pk2(db1_0, 0.f), aD1 = pk2(db1_1, 0.f);
#pragma unroll
            for (int k = 0; k < 8; k++) {
                aD0 = ffma2(wd0[k], hhp[k], aD0);
                aD1 = ffma2(wd1[k], hhp[k], aD1);
            }
            float d0l, d0h, d1l, d1h;
            upk2(d0l, d0h, aD0); upk2(d1l, d1h, aD1);
            const float d0 = mytanh(d0l + d0h);
            const float d1 = mytanh(d1l + d1h);
            const u64 dpk = pk2(d0, d1);
            float pp0, pp1, pp2, pp3;
            { float lo, hi;
              upk2(lo, hi, fmul2(w2p[0], dpk)); pp0 = lo + hi;
              upk2(lo, hi, fmul2(w2p[1], dpk)); pp1 = lo + hi;
              upk2(lo, hi, fmul2(w2p[2], dpk)); pp2 = lo + hi;
              upk2(lo, hi, fmul2(w2p[3], dpk)); pp3 = lo + hi; }
            float q01  = (lane & 1) ? pp1 : pp0;
            float q01b = (lane & 1) ? pp0 : pp1;
            q01 += __shfl_xor_sync(0xffffffffu, q01b, 1);
            float q23  = (lane & 1) ? pp3 : pp2;
            float q23b = (lane & 1) ? pp2 : pp3;
            q23 += __shfl_xor_sync(0xffffffffu, q23b, 1);
            float qq  = (lane & 2) ? q23 : q01;
            float qqb = (lane & 2) ? q01 : q23;
            qq += __shfl_xor_sync(0xffffffffu, qqb, 2);
            qq += __shfl_xor_sync(0xffffffffu, qq, 4);
            qq += __shfl_xor_sync(0xffffffffu, qq, 8);
            if (l > 0 && active && lane < 4)
                out_x[((size_t)(l - 1) * B_ + bb) * 4 + lane] = qq + db2;
        }
#pragma unroll
        for (int j = 0; j < 8; j++) { cr[j] = nr[j]; cz[j] = nz[j]; cn[j] = nn_[j]; }
    }

    // tail: decode final hidden (in s_h[0]) → out_x[L-1]
    {
        const ulonglong2* sh = (const ulonglong2*)s_h[0][g];
        const ulonglong2 q0 = sh[0], q1 = sh[1], q2 = sh[2], q3 = sh[3];
        const u64 hhp[8] = {q0.x, q0.y, q1.x, q1.y, q2.x, q2.y, q3.x, q3.y};
        u64 aD0 = pk2(db1_0, 0.f), aD1 = pk2(db1_1, 0.f);
#pragma unroll
        for (int k = 0; k < 8; k++) {
            aD0 = ffma2(wd0[k], hhp[k], aD0);
            aD1 = ffma2(wd1[k], hhp[k], aD1);
        }
        float d0l, d0h, d1l, d1h;
        upk2(d0l, d0h, aD0); upk2(d1l, d1h, aD1);
        const float d0 = mytanh(d0l + d0h);
        const float d1 = mytanh(d1l + d1h);
        const u64 dpk = pk2(d0, d1);
        float pp0, pp1, pp2, pp3;
        { float lo, hi;
          upk2(lo, hi, fmul2(w2p[0], dpk)); pp0 = lo + hi;
          upk2(lo, hi, fmul2(w2p[1], dpk)); pp1 = lo + hi;
          upk2(lo, hi, fmul2(w2p[2], dpk)); pp2 = lo + hi;
          upk2(lo, hi, fmul2(w2p[3], dpk)); pp3 = lo + hi; }
        float q01  = (lane & 1) ? pp1 : pp0;
        float q01b = (lane & 1) ? pp0 : pp1;
        q01 += __shfl_xor_sync(0xffffffffu, q01b, 1);
        float q23  = (lane & 1) ? pp3 : pp2;
        float q23b = (lane & 1) ? pp2 : pp3;
        q23 += __shfl_xor_sync(0xffffffffu, q23b, 1);
        float qq  = (lane & 2) ? q23 : q01;
        float qqb = (lane & 2) ? q01 : q23;
        qq += __shfl_xor_sync(0xffffffffu, qqb, 2);
        qq += __shfl_xor_sync(0xffffffffu, qq, 4);
        qq += __shfl_xor_sync(0xffffffffu, qq, 8);
        if (active && lane < 4)
            out_x[((size_t)(L_ - 1) * B_ + bb) * 4 + lane] = qq + db2;
    }
}

// ============================================================================
extern "C" void kernel_launch(void* const* d_in, const int* in_sizes, int n_in,
                              void* d_out, int out_size) {
    const float* u_in   = (const float*)d_in[0];
    const float* x_in   = (const float*)d_in[1];
    const float* pu_W1  = (const float*)d_in[2];
    const float* pu_b1  = (const float*)d_in[3];
    const float* pu_W2  = (const float*)d_in[4];
    const float* pu_b2  = (const float*)d_in[5];
    const float* px_W1  = (const float*)d_in[6];
    const float* px_b1  = (const float*)d_in[7];
    const float* px_W2  = (const float*)d_in[8];
    const float* px_b2  = (const float*)d_in[9];
    const float* W_ih   = (const float*)d_in[10];
    const float* b_ih   = (const float*)d_in[11];
    const float* W_hh   = (const float*)d_in[12];
    const float* b_hh   = (const float*)d_in[13];
    const float* dec_W1 = (const float*)d_in[14];
    const float* dec_b1 = (const float*)d_in[15];
    const float* dec_W2 = (const float*)d_in[16];
    const float* dec_b2 = (const float*)d_in[17];

    float* out_x = (float*)d_out;                          // [L,B,4]
    float* out_h = (float*)d_out + (size_t)L_ * B_ * 4;    // [L,B,16]

    k1_gates<<<NE / K1T, K1T>>>(u_in, x_in, pu_W1, pu_b1, pu_W2, pu_b2,
                                px_W1, px_b1, px_W2, px_b2, W_ih, b_ih);
    k2_recur<<<(B_ + BPC - 1) / BPC, NT2>>>(W_hh, b_hh,
                                            dec_W1, dec_b1, dec_W2, dec_b2,
                                            out_h, out_x);
}